// round 3
// baseline (speedup 1.0000x reference)
#include <cuda_runtime.h>
#include <cstdint>

#define DIM        2048
#define NEXP       8
#define TILE_T     64          // tokens per block (2 per lane)
#define WARPS      8
#define THREADS    (WARPS * 32)
#define COLS_PER_WARP (DIM / WARPS)   // 256
#define STAGE_COLS 8
#define NSTAGES    (COLS_PER_WARP / STAGE_COLS)  // 32
#define NBUF       6
#define CHUNKS     (STAGE_COLS / 4)   // 2 float4 per row per stage
#define BUF_F4     (TILE_T * CHUNKS)  // 128 float4 per buffer (2 KB)
#define MOE_COEFF  0.01f
#define MAX_BLOCKS 1024

__device__ float        g_imp_part[MAX_BLOCKS * NEXP];
__device__ float        g_load_part[MAX_BLOCKS * NEXP];
__device__ unsigned int g_ticket = 0;

__device__ __forceinline__ unsigned long long ffma2(unsigned long long a,
                                                    unsigned long long b,
                                                    unsigned long long c) {
    unsigned long long d;
    asm("fma.rn.f32x2 %0, %1, %2, %3;" : "=l"(d) : "l"(a), "l"(b), "l"(c));
    return d;
}
__device__ __forceinline__ unsigned long long pack2(float x, float y) {
    unsigned long long d;
    asm("mov.b64 %0, {%1, %2};" : "=l"(d) : "f"(x), "f"(y));
    return d;
}
__device__ __forceinline__ float2 unpack2(unsigned long long d) {
    float2 r;
    asm("mov.b64 {%0, %1}, %2;" : "=f"(r.x), "=f"(r.y) : "l"(d));
    return r;
}

__global__ void __launch_bounds__(THREADS)
gate_kernel(const float* __restrict__ x, const float* __restrict__ W,
            float* __restrict__ out, int half, int ntok, int auxPos) {
    extern __shared__ float4 smem[];
    // x staging: [8 warps][NBUF=6][64 rows][2 chunks] float4 = 96 KB.
    // logits buffer is UNIONED over the same smem (used only after compute).
    float* logitsBuf = reinterpret_cast<float*>(smem);

    const int tid  = threadIdx.x;
    const int w    = tid >> 5;
    const int lane = tid & 31;
    const int tok0 = blockIdx.x * TILE_T;
    const int colBase = w * COLS_PER_WARP;
    float4* xb = smem + w * (NBUF * BUF_F4);

    const int c_st  = lane & 1;      // staging chunk (0..1) — pairs cover 32B sectors
    const int r0_st = lane >> 1;     // staging base row (0..15)

    // ---- issue one stage of cp.async (2 KB: 64 rows x 8 cols) ----
    #define ISSUE_STAGE(s)                                                      \
    {                                                                           \
        int bi_ = (s) % NBUF;                                                   \
        const float* src0_ = x + (size_t)(tok0 + r0_st) * DIM                   \
                               + colBase + (s) * STAGE_COLS + c_st * 4;         \
        _Pragma("unroll")                                                       \
        for (int j = 0; j < 4; j++) {                                           \
            int r_ = r0_st + j * 16;                                            \
            const float* src_ = src0_ + (size_t)j * 16 * DIM;                   \
            float4* dst_ = xb + bi_ * BUF_F4 + r_ * CHUNKS                      \
                              + (c_st ^ ((r_ >> 2) & 1));                       \
            unsigned int da_ = (unsigned int)__cvta_generic_to_shared(dst_);    \
            asm volatile("cp.async.cg.shared.global [%0], [%1], 16;"            \
                         :: "r"(da_), "l"(src_));                               \
        }                                                                       \
        asm volatile("cp.async.commit_group;");                                 \
    }

    unsigned long long accA[NEXP], accB[NEXP];
    #pragma unroll
    for (int e = 0; e < NEXP; e++) { accA[e] = 0ULL; accB[e] = 0ULL; }

    // prologue: fill 5 of 6 buffers
    ISSUE_STAGE(0); ISSUE_STAGE(1); ISSUE_STAGE(2); ISSUE_STAGE(3); ISSUE_STAGE(4);

    const float4* W4 = reinterpret_cast<const float4*>(W);
    const int swz = (lane >> 2) & 1;   // rows lane and lane+32 share parity

    #pragma unroll 1
    for (int s = 0; s < NSTAGES; s++) {
        asm volatile("cp.async.wait_group 4;");   // group s complete
        __syncwarp();
        // issue next stage BEFORE compute (keeps queue fed during FFMA burst)
        if (s + NBUF - 1 < NSTAGES) {
            ISSUE_STAGE(s + NBUF - 1);
        } else {
            asm volatile("cp.async.commit_group;");   // keep group count exact
        }
        const int bi = s % NBUF;
        const float4* xsA = xb + bi * BUF_F4 + lane * CHUNKS;
        const float4* xsB = xb + bi * BUF_F4 + (lane + 32) * CHUNKS;
        const int wcol = (colBase + s * STAGE_COLS) >> 2;   // float4 index
        #pragma unroll
        for (int i = 0; i < CHUNKS; i++) {
            float4 xvA = xsA[i ^ swz];
            float4 xvB = xsB[i ^ swz];
            unsigned long long aLo = pack2(xvA.x, xvA.y);
            unsigned long long aHi = pack2(xvA.z, xvA.w);
            unsigned long long bLo = pack2(xvB.x, xvB.y);
            unsigned long long bHi = pack2(xvB.z, xvB.w);
            #pragma unroll
            for (int e = 0; e < NEXP; e++) {
                float4 wv = __ldg(&W4[e * (DIM / 4) + wcol + i]);
                unsigned long long wLo = pack2(wv.x, wv.y);
                unsigned long long wHi = pack2(wv.z, wv.w);
                accA[e] = ffma2(aLo, wLo, accA[e]);
                accA[e] = ffma2(aHi, wHi, accA[e]);
                accB[e] = ffma2(bLo, wLo, accB[e]);
                accB[e] = ffma2(bHi, wHi, accB[e]);
            }
        }
        __syncwarp();
    }

    // Finish pending cp.async, then reuse staging smem for logits.
    asm volatile("cp.async.wait_group 0;");
    __syncthreads();

    // per-lane partial logits -> smem (row stride 9 words: conflict-free)
    {
        float* lrowA = logitsBuf + (w * TILE_T + lane) * 9;
        float* lrowB = logitsBuf + (w * TILE_T + lane + 32) * 9;
        #pragma unroll
        for (int e = 0; e < NEXP; e++) {
            float2 tA = unpack2(accA[e]);
            float2 tB = unpack2(accB[e]);
            lrowA[e] = tA.x + tA.y;
            lrowB[e] = tB.x + tB.y;
        }
    }
    __syncthreads();

    if (w == 0) {
        float impLoc[NEXP];
        #pragma unroll
        for (int e = 0; e < NEXP; e++) impLoc[e] = 0.0f;
        int top1[2];

        #pragma unroll
        for (int half_t = 0; half_t < 2; half_t++) {
            const int tloc = lane + half_t * 32;
            float lg[NEXP];
            #pragma unroll
            for (int e = 0; e < NEXP; e++) {
                float sum = 0.0f;
                #pragma unroll
                for (int ww = 0; ww < WARPS; ww++)
                    sum += logitsBuf[(ww * TILE_T + tloc) * 9 + e];
                lg[e] = sum;
            }
            float m = lg[0];
            #pragma unroll
            for (int e = 1; e < NEXP; e++) m = fmaxf(m, lg[e]);
            float p[NEXP], psum = 0.0f;
            #pragma unroll
            for (int e = 0; e < NEXP; e++) { p[e] = __expf(lg[e] - m); psum += p[e]; }
            float inv = 1.0f / psum;
            #pragma unroll
            for (int e = 0; e < NEXP; e++) { p[e] *= inv; impLoc[e] += p[e]; }

            // top-1 / top-2 (first max wins: matches jax tie rule)
            int e0 = 0; float v0 = p[0];
            #pragma unroll
            for (int e = 1; e < NEXP; e++) if (p[e] > v0) { v0 = p[e]; e0 = e; }
            int e1 = (e0 == 0) ? 1 : 0; float v1 = p[e1];
            #pragma unroll
            for (int e = 0; e < NEXP; e++)
                if (e != e0 && p[e] > v1) { v1 = p[e]; e1 = e; }
            top1[half_t] = e0;

            float rs = 1.0f / (v0 + v1);
            const int tok = tok0 + tloc;
            out[tok * 2 + 0] = v0 * rs;
            out[tok * 2 + 1] = v1 * rs;
            out[half + tok * 2 + 0] = (float)e0;
            out[half + tok * 2 + 1] = (float)e1;
        }

        // per-block aux statistics -> scratch (no atomics, no pre-zero kernel)
        #pragma unroll
        for (int e = 0; e < NEXP; e++) {
            float v = impLoc[e];
            #pragma unroll
            for (int o = 16; o; o >>= 1) v += __shfl_xor_sync(0xffffffffu, v, o);
            unsigned bal0 = __ballot_sync(0xffffffffu, top1[0] == e);
            unsigned bal1 = __ballot_sync(0xffffffffu, top1[1] == e);
            if (lane == 0) {
                g_imp_part[blockIdx.x * NEXP + e]  = v;
                g_load_part[blockIdx.x * NEXP + e] = (float)(__popc(bal0) + __popc(bal1));
            }
        }
        __threadfence();

        // last-block finalize (deterministic; ticket resets itself each run)
        unsigned old = 0;
        if (lane == 0) old = atomicAdd(&g_ticket, 1u);
        old = __shfl_sync(0xffffffffu, old, 0);
        if (old == gridDim.x - 1) {
            __threadfence();
            const int e = lane & 7;
            const int q = lane >> 3;            // quarter of blocks
            const int nblk = gridDim.x;
            const int per = nblk / 4;
            float si = 0.0f, sl = 0.0f;
            for (int b = q * per; b < (q + 1) * per; b++) {
                si += __ldcg(&g_imp_part[b * NEXP + e]);
                sl += __ldcg(&g_load_part[b * NEXP + e]);
            }
            si += __shfl_xor_sync(0xffffffffu, si, 8);
            si += __shfl_xor_sync(0xffffffffu, si, 16);
            sl += __shfl_xor_sync(0xffffffffu, sl, 8);
            sl += __shfl_xor_sync(0xffffffffu, sl, 16);
            float invN = 1.0f / (float)ntok;
            float prod = (si * invN) * (sl * invN);
            prod += __shfl_xor_sync(0xffffffffu, prod, 1);
            prod += __shfl_xor_sync(0xffffffffu, prod, 2);
            prod += __shfl_xor_sync(0xffffffffu, prod, 4);
            if (lane == 0) {
                out[auxPos] = (float)NEXP * prod * MOE_COEFF;
                g_ticket = 0;   // reset for next graph replay
            }
        }
    }
}

extern "C" void kernel_launch(void* const* d_in, const int* in_sizes, int n_in,
                              void* d_out, int out_size) {
    const float* x = (const float*)d_in[0];
    const float* W = (const float*)d_in[1];
    float* out = (float*)d_out;

    const int ntok = in_sizes[0] / DIM;          // 16384
    const int half = (out_size - 1) / 2;         // 32768
    const int grid = ntok / TILE_T;              // 256
    const int smemB = WARPS * NBUF * BUF_F4 * 16; // 98304 (logits unioned inside)

    static bool attrDone = false;
    if (!attrDone) {
        cudaFuncSetAttribute(gate_kernel,
                             cudaFuncAttributeMaxDynamicSharedMemorySize, smemB);
        attrDone = true;
    }

    gate_kernel<<<grid, THREADS, smemB>>>(x, W, out, half, ntok, out_size - 1);
}

// round 4
// speedup vs baseline: 1.0179x; 1.0179x over previous
#include <cuda_runtime.h>
#include <cstdint>

#define DIM         2048
#define NEXP        8
#define TILE_T      64                      // tokens per block
#define WARPS       8
#define THREADS     256
#define STAGE_COLS  64
#define NSTAGES     (DIM / STAGE_COLS)      // 32
#define NBUF        6
#define ROW_BYTES   272                     // 256 B data + 16 B pad (bank rotate 4)
#define STAGE_BYTES (TILE_T * ROW_BYTES)    // 17408
#define STAGE_TX    (TILE_T * STAGE_COLS * 4) // 16384 actual bytes per stage
#define MBAR_OFF    (NBUF * STAGE_BYTES)    // 104448
#define SMEM_TOTAL  (MBAR_OFF + NBUF * 16)  // + full/empty pairs
#define MOE_COEFF   0.01f
#define MAX_BLOCKS  1024

__device__ float        g_imp_part[MAX_BLOCKS * NEXP];
__device__ float        g_load_part[MAX_BLOCKS * NEXP];
__device__ unsigned int g_ticket = 0;

__device__ __forceinline__ unsigned long long ffma2(unsigned long long a,
                                                    unsigned long long b,
                                                    unsigned long long c) {
    unsigned long long d;
    asm("fma.rn.f32x2 %0, %1, %2, %3;" : "=l"(d) : "l"(a), "l"(b), "l"(c));
    return d;
}
__device__ __forceinline__ unsigned long long pack2(float x, float y) {
    unsigned long long d;
    asm("mov.b64 %0, {%1, %2};" : "=l"(d) : "f"(x), "f"(y));
    return d;
}
__device__ __forceinline__ float2 unpack2(unsigned long long d) {
    float2 r;
    asm("mov.b64 {%0, %1}, %2;" : "=f"(r.x), "=f"(r.y) : "l"(d));
    return r;
}

__device__ __forceinline__ void mbar_init(unsigned int a, unsigned int cnt) {
    asm volatile("mbarrier.init.shared.b64 [%0], %1;" :: "r"(a), "r"(cnt) : "memory");
}
__device__ __forceinline__ void mbar_arrive(unsigned int a) {
    asm volatile("mbarrier.arrive.shared.b64 _, [%0];" :: "r"(a) : "memory");
}
__device__ __forceinline__ void mbar_expect_tx(unsigned int a, unsigned int bytes) {
    asm volatile("mbarrier.arrive.expect_tx.shared.b64 _, [%0], %1;"
                 :: "r"(a), "r"(bytes) : "memory");
}
__device__ __forceinline__ void mbar_wait_acq(unsigned int a, unsigned int parity) {
    asm volatile(
        "{\n\t.reg .pred P1;\n\t"
        "WL_%=:\n\t"
        "mbarrier.try_wait.parity.acquire.cta.shared::cta.b64 P1, [%0], %1, 0x989680;\n\t"
        "@P1 bra.uni WD_%=;\n\t"
        "bra.uni WL_%=;\n\t"
        "WD_%=:\n\t}"
        :: "r"(a), "r"(parity) : "memory");
}
__device__ __forceinline__ void mbar_wait_rel(unsigned int a, unsigned int parity) {
    asm volatile(
        "{\n\t.reg .pred P1;\n\t"
        "WL_%=:\n\t"
        "mbarrier.try_wait.parity.relaxed.cta.shared::cta.b64 P1, [%0], %1, 0x989680;\n\t"
        "@P1 bra.uni WD_%=;\n\t"
        "bra.uni WL_%=;\n\t"
        "WD_%=:\n\t}"
        :: "r"(a), "r"(parity) : "memory");
}
__device__ __forceinline__ void bulk_copy(unsigned int dst, const void* src,
                                          unsigned int bytes, unsigned int mbar) {
    asm volatile(
        "cp.async.bulk.shared::cta.global.mbarrier::complete_tx::bytes [%0], [%1], %2, [%3];"
        :: "r"(dst), "l"(src), "r"(bytes), "r"(mbar) : "memory");
}

__global__ void __launch_bounds__(THREADS)
gate_kernel(const float* __restrict__ x, const float* __restrict__ W,
            float* __restrict__ out, int half, int ntok, int auxPos) {
    extern __shared__ char smem[];
    const unsigned int sbase = (unsigned int)__cvta_generic_to_shared(smem);
    float* logitsBuf = reinterpret_cast<float*>(smem);  // union over staging, used after loop

    const int tid  = threadIdx.x;
    const int w    = tid >> 5;
    const int lane = tid & 31;
    const int tok0 = blockIdx.x * TILE_T;
    const bool leader = (lane == 0);

    const unsigned int fullBar0  = sbase + MBAR_OFF;       // full[i]  at +i*16
    const unsigned int emptyBar0 = sbase + MBAR_OFF + 8;   // empty[i] at +i*16+8

    if (tid == 0) {
        #pragma unroll
        for (int i = 0; i < NBUF; i++) {
            mbar_init(fullBar0 + i * 16, WARPS);     // 8 leader arrivals + tx bytes
            mbar_init(emptyBar0 + i * 16, THREADS);  // all threads arrive
        }
    }
    __syncthreads();

    // leader of warp w stages rows [w*8, w*8+8) of stage t
    const float* myRow0 = x + (size_t)(tok0 + w * 8) * DIM;
    #define ISSUE_STAGE(t)                                                      \
    {                                                                           \
        const int bi_ = (t) % NBUF;                                             \
        mbar_wait_rel(emptyBar0 + bi_ * 16, 1u ^ (((t) / NBUF) & 1));           \
        mbar_expect_tx(fullBar0 + bi_ * 16, STAGE_TX / WARPS);                  \
        const float* src_ = myRow0 + (t) * STAGE_COLS;                          \
        unsigned int dst_ = sbase + bi_ * STAGE_BYTES + (w * 8) * ROW_BYTES;    \
        _Pragma("unroll")                                                       \
        for (int r = 0; r < 8; r++)                                             \
            bulk_copy(dst_ + r * ROW_BYTES, src_ + (size_t)r * DIM,             \
                      STAGE_COLS * 4, fullBar0 + bi_ * 16);                     \
    }

    if (leader) {
        #pragma unroll
        for (int t = 0; t < NBUF - 1; t++) ISSUE_STAGE(t);
    }

    unsigned long long accA[NEXP], accB[NEXP];
    #pragma unroll
    for (int e = 0; e < NEXP; e++) { accA[e] = 0ULL; accB[e] = 0ULL; }

    const float4* W4 = reinterpret_cast<const float4*>(W);
    // lane handles tokens (lane) and (lane+32); warp w owns cols w*8..w*8+7 of each stage
    const int rowOffA = lane * ROW_BYTES + w * 32;
    const int rowOffB = (lane + 32) * ROW_BYTES + w * 32;

    #pragma unroll 1
    for (int s = 0; s < NSTAGES; s++) {
        const int bi = s % NBUF;
        mbar_wait_acq(fullBar0 + bi * 16, (s / NBUF) & 1);
        // refill ahead (depth NBUF-1)
        if (leader) {
            const int t = s + NBUF - 1;
            if (t < NSTAGES) ISSUE_STAGE(t);
        }
        const char* base = smem + bi * STAGE_BYTES;
        float4 a0 = *reinterpret_cast<const float4*>(base + rowOffA);
        float4 a1 = *reinterpret_cast<const float4*>(base + rowOffA + 16);
        float4 b0 = *reinterpret_cast<const float4*>(base + rowOffB);
        float4 b1 = *reinterpret_cast<const float4*>(base + rowOffB + 16);
        unsigned long long aP0 = pack2(a0.x, a0.y), aP1 = pack2(a0.z, a0.w);
        unsigned long long aP2 = pack2(a1.x, a1.y), aP3 = pack2(a1.z, a1.w);
        unsigned long long bP0 = pack2(b0.x, b0.y), bP1 = pack2(b0.z, b0.w);
        unsigned long long bP2 = pack2(b1.x, b1.y), bP3 = pack2(b1.z, b1.w);
        const int wcol = s * (STAGE_COLS / 4) + w * 2;
        #pragma unroll
        for (int e = 0; e < NEXP; e++) {
            float4 wv0 = __ldg(&W4[e * (DIM / 4) + wcol]);
            float4 wv1 = __ldg(&W4[e * (DIM / 4) + wcol + 1]);
            unsigned long long w0 = pack2(wv0.x, wv0.y), w1 = pack2(wv0.z, wv0.w);
            unsigned long long w2 = pack2(wv1.x, wv1.y), w3 = pack2(wv1.z, wv1.w);
            accA[e] = ffma2(aP0, w0, accA[e]);
            accA[e] = ffma2(aP1, w1, accA[e]);
            accA[e] = ffma2(aP2, w2, accA[e]);
            accA[e] = ffma2(aP3, w3, accA[e]);
            accB[e] = ffma2(bP0, w0, accB[e]);
            accB[e] = ffma2(bP1, w1, accB[e]);
            accB[e] = ffma2(bP2, w2, accB[e]);
            accB[e] = ffma2(bP3, w3, accB[e]);
        }
        mbar_arrive(emptyBar0 + bi * 16);   // release: orders the LDS above
    }
    __syncthreads();

    // per-lane partial logits -> smem (row stride 9 words: conflict-free)
    {
        float* lrowA = logitsBuf + (w * TILE_T + lane) * 9;
        float* lrowB = logitsBuf + (w * TILE_T + lane + 32) * 9;
        #pragma unroll
        for (int e = 0; e < NEXP; e++) {
            float2 tA = unpack2(accA[e]);
            float2 tB = unpack2(accB[e]);
            lrowA[e] = tA.x + tA.y;
            lrowB[e] = tB.x + tB.y;
        }
    }
    __syncthreads();

    if (w == 0) {
        float impLoc[NEXP];
        #pragma unroll
        for (int e = 0; e < NEXP; e++) impLoc[e] = 0.0f;
        int top1[2];

        #pragma unroll
        for (int half_t = 0; half_t < 2; half_t++) {
            const int tloc = lane + half_t * 32;
            float lg[NEXP];
            #pragma unroll
            for (int e = 0; e < NEXP; e++) {
                float sum = 0.0f;
                #pragma unroll
                for (int ww = 0; ww < WARPS; ww++)
                    sum += logitsBuf[(ww * TILE_T + tloc) * 9 + e];
                lg[e] = sum;
            }
            float m = lg[0];
            #pragma unroll
            for (int e = 1; e < NEXP; e++) m = fmaxf(m, lg[e]);
            float p[NEXP], psum = 0.0f;
            #pragma unroll
            for (int e = 0; e < NEXP; e++) { p[e] = __expf(lg[e] - m); psum += p[e]; }
            float inv = 1.0f / psum;
            #pragma unroll
            for (int e = 0; e < NEXP; e++) { p[e] *= inv; impLoc[e] += p[e]; }

            // top-1 / top-2 (first max wins: matches jax tie rule)
            int e0 = 0; float v0 = p[0];
            #pragma unroll
            for (int e = 1; e < NEXP; e++) if (p[e] > v0) { v0 = p[e]; e0 = e; }
            int e1 = (e0 == 0) ? 1 : 0; float v1 = p[e1];
            #pragma unroll
            for (int e = 0; e < NEXP; e++)
                if (e != e0 && p[e] > v1) { v1 = p[e]; e1 = e; }
            top1[half_t] = e0;

            float rs = 1.0f / (v0 + v1);
            const int tok = tok0 + tloc;
            out[tok * 2 + 0] = v0 * rs;
            out[tok * 2 + 1] = v1 * rs;
            out[half + tok * 2 + 0] = (float)e0;
            out[half + tok * 2 + 1] = (float)e1;
        }

        // per-block aux statistics -> scratch (no atomics, no pre-zero kernel)
        #pragma unroll
        for (int e = 0; e < NEXP; e++) {
            float v = impLoc[e];
            #pragma unroll
            for (int o = 16; o; o >>= 1) v += __shfl_xor_sync(0xffffffffu, v, o);
            unsigned bal0 = __ballot_sync(0xffffffffu, top1[0] == e);
            unsigned bal1 = __ballot_sync(0xffffffffu, top1[1] == e);
            if (lane == 0) {
                g_imp_part[blockIdx.x * NEXP + e]  = v;
                g_load_part[blockIdx.x * NEXP + e] = (float)(__popc(bal0) + __popc(bal1));
            }
        }
        __threadfence();

        // last-block finalize (deterministic; ticket resets itself each run)
        unsigned old = 0;
        if (lane == 0) old = atomicAdd(&g_ticket, 1u);
        old = __shfl_sync(0xffffffffu, old, 0);
        if (old == gridDim.x - 1) {
            __threadfence();
            const int e = lane & 7;
            const int q = lane >> 3;
            const int nblk = gridDim.x;
            const int per = nblk / 4;
            float si = 0.0f, sl = 0.0f;
            for (int b = q * per; b < (q + 1) * per; b++) {
                si += __ldcg(&g_imp_part[b * NEXP + e]);
                sl += __ldcg(&g_load_part[b * NEXP + e]);
            }
            si += __shfl_xor_sync(0xffffffffu, si, 8);
            si += __shfl_xor_sync(0xffffffffu, si, 16);
            sl += __shfl_xor_sync(0xffffffffu, sl, 8);
            sl += __shfl_xor_sync(0xffffffffu, sl, 16);
            float invN = 1.0f / (float)ntok;
            float prod = (si * invN) * (sl * invN);
            prod += __shfl_xor_sync(0xffffffffu, prod, 1);
            prod += __shfl_xor_sync(0xffffffffu, prod, 2);
            prod += __shfl_xor_sync(0xffffffffu, prod, 4);
            if (lane == 0) {
                out[auxPos] = (float)NEXP * prod * MOE_COEFF;
                g_ticket = 0;
            }
        }
    }
}

extern "C" void kernel_launch(void* const* d_in, const int* in_sizes, int n_in,
                              void* d_out, int out_size) {
    const float* x = (const float*)d_in[0];
    const float* W = (const float*)d_in[1];
    float* out = (float*)d_out;

    const int ntok = in_sizes[0] / DIM;          // 16384
    const int half = (out_size - 1) / 2;         // 32768
    const int grid = ntok / TILE_T;              // 256

    static bool attrDone = false;
    if (!attrDone) {
        cudaFuncSetAttribute(gate_kernel,
                             cudaFuncAttributeMaxDynamicSharedMemorySize, SMEM_TOTAL);
        attrDone = true;
    }

    gate_kernel<<<grid, THREADS, SMEM_TOTAL>>>(x, W, out, half, ntok, out_size - 1);
}